// round 3
// baseline (speedup 1.0000x reference)
#include <cuda_runtime.h>

#define N_NODES 20000
#define N_EDGES 320000
#define N_GRAPH 32
#define HD 64
#define H 4
#define C 64
#define L 3
#define E2 (N_EDGES + N_NODES)
#define HC (H*C)   // 256

// ---------------- scratch (static device globals; allocation-free) ----------------
static __device__ float d_h[N_NODES*HD];       // node features (ping through layers)
static __device__ float d_xp[N_NODES*HC];      // per-layer projected features [N,H,C]
static __device__ float d_acc[N_NODES*HC];     // aggregation accumulator
static __device__ float d_ea[N_EDGES*HD];      // edge embeddings (relu)
static __device__ float d_eaself[N_NODES*HD];  // sum then mean of incoming ea (self-loop attr)
static __device__ float d_deg[N_NODES];
static __device__ float d_aed[L*E2*H];         // precomputed attention edge terms, all layers
static __device__ float d_as[N_NODES*H];
static __device__ float d_ad[N_NODES*H];
static __device__ float d_alpha[E2*H];
static __device__ float d_m[N_NODES*H];
static __device__ float d_den[N_NODES*H];
static __device__ float d_pool[N_GRAPH*HD];
static __device__ float d_cnt[N_GRAPH];
static __device__ float d_wevec[L*H*HD];       // We[:,hC:(h+1)C] @ a_e[h]

// ---------------- helpers ----------------
__device__ __forceinline__ void atomicMaxF(float* addr, float val) {
    int* ia = (int*)addr;
    int old = __float_as_int(*addr);
    while (__int_as_float(old) < val) {
        int assumed = old;
        old = atomicCAS(ia, assumed, __float_as_int(val));
        if (old == assumed) break;
    }
}

// ---------------- kernels ----------------
__global__ void k_zero() {
    int tid = blockIdx.x*blockDim.x + threadIdx.x;
    if (tid < N_NODES*HD) d_eaself[tid] = 0.f;
    if (tid < N_NODES)    d_deg[tid] = 0.f;
    if (tid < N_GRAPH*HD) d_pool[tid] = 0.f;
    if (tid < N_GRAPH)    d_cnt[tid] = 0.f;
}

__global__ void k_node_embed(const float* __restrict__ x,
                             const float* __restrict__ W,
                             const float* __restrict__ b) {
    int tid = blockIdx.x*blockDim.x + threadIdx.x;
    if (tid >= N_NODES*HD) return;
    int n = tid >> 6, j = tid & 63;
    float a = b[j];
    #pragma unroll
    for (int k = 0; k < 3; k++) a += x[n*3+k]*W[k*HD+j];
    d_h[tid] = fmaxf(a, 0.f);
}

__global__ void k_edge_embed(const float* __restrict__ eattr,
                             const float* __restrict__ W,
                             const float* __restrict__ b) {
    int tid = blockIdx.x*blockDim.x + threadIdx.x;
    if (tid >= N_EDGES*HD) return;
    int e = tid >> 6, j = tid & 63;
    float a = b[j];
    #pragma unroll
    for (int k = 0; k < 4; k++) a += eattr[e*4+k]*W[k*HD+j];
    d_ea[tid] = fmaxf(a, 0.f);
}

// wevec[l,h,k] = sum_c lin_eW[l][k, h*C+c] * att_e[l][h,c]
__global__ void k_wevec(const float* __restrict__ lin_eW,
                        const float* __restrict__ att_e) {
    int tid = blockIdx.x*blockDim.x + threadIdx.x;
    if (tid >= L*H*HD) return;
    int l = tid / (H*HD), r = tid % (H*HD), h = r / HD, k = r % HD;
    const float* We = lin_eW + (size_t)l*HD*HC;
    const float* ae = att_e + l*HC;
    float a = 0.f;
    #pragma unroll 8
    for (int c = 0; c < C; c++) a += We[k*HC + h*C + c]*ae[h*C + c];
    d_wevec[tid] = a;  // layout l*256 + h*64 + k == tid
}

__global__ void k_degsum(const int* __restrict__ ei) {
    int tid = blockIdx.x*blockDim.x + threadIdx.x;
    if (tid >= N_EDGES*HD) return;
    int e = tid >> 6, j = tid & 63;
    int dst = ei[N_EDGES + e];
    atomicAdd(&d_eaself[dst*HD+j], d_ea[tid]);
    if (j == 0) atomicAdd(&d_deg[dst], 1.f);
}

__global__ void k_eaself() {
    int tid = blockIdx.x*blockDim.x + threadIdx.x;
    if (tid >= N_NODES*HD) return;
    int n = tid >> 6;
    d_eaself[tid] = d_eaself[tid] / fmaxf(d_deg[n], 1.f);
}

// a_ed for all L layers, all E2 edges (incl. self loops)
__global__ void k_aed() {
    int tid = blockIdx.x*blockDim.x + threadIdx.x;
    if (tid >= E2*L*H) return;
    int e = tid / (L*H), r = tid % (L*H), l = r >> 2, h = r & 3;
    const float* row = (e < N_EDGES) ? &d_ea[(size_t)e*HD] : &d_eaself[(size_t)(e-N_EDGES)*HD];
    const float* w = &d_wevec[l*H*HD + h*HD];
    float a = 0.f;
    #pragma unroll 8
    for (int k = 0; k < HD; k++) a += row[k]*w[k];
    d_aed[((size_t)l*E2 + e)*H + h] = a;
}

// per-layer: xp = h @ W, a_src/a_dst reductions, plus per-node inits
__global__ void k_xp(const float* __restrict__ linW,
                     const float* __restrict__ asrc,
                     const float* __restrict__ adst) {
    int n = blockIdx.x, j = threadIdx.x;
    __shared__ float hrow[HD];
    __shared__ float wss[8], wsd[8];
    if (j < HD) hrow[j] = d_h[n*HD+j];
    __syncthreads();
    float a = 0.f;
    #pragma unroll 16
    for (int k = 0; k < HD; k++) a += hrow[k]*linW[k*HC+j];
    d_xp[(size_t)n*HC+j] = a;
    d_acc[(size_t)n*HC+j] = 0.f;
    float ps = a * asrc[j];
    float pd = a * adst[j];
    #pragma unroll
    for (int o = 16; o > 0; o >>= 1) {
        ps += __shfl_down_sync(0xffffffffu, ps, o);
        pd += __shfl_down_sync(0xffffffffu, pd, o);
    }
    int w = j >> 5;
    if ((j & 31) == 0) { wss[w] = ps; wsd[w] = pd; }
    __syncthreads();
    if (j < H) {
        d_as[n*H+j] = wss[2*j] + wss[2*j+1];
        d_ad[n*H+j] = wsd[2*j] + wsd[2*j+1];
        d_m[n*H+j]  = -1e30f;
        d_den[n*H+j] = 0.f;
    }
}

__global__ void k_alpha(const int* __restrict__ ei, int l) {
    int tid = blockIdx.x*blockDim.x + threadIdx.x;
    if (tid >= E2*H) return;
    int e = tid >> 2, h = tid & 3;
    int src, dst;
    if (e < N_EDGES) { src = ei[e]; dst = ei[N_EDGES+e]; }
    else             { src = dst = e - N_EDGES; }
    float v = d_as[src*H+h] + d_ad[dst*H+h] + d_aed[((size_t)l*E2 + e)*H + h];
    v = (v > 0.f) ? v : 0.2f*v;   // leaky_relu(0.2)
    d_alpha[tid] = v;
    atomicMaxF(&d_m[dst*H+h], v);
}

__global__ void k_exp(const int* __restrict__ ei) {
    int tid = blockIdx.x*blockDim.x + threadIdx.x;
    if (tid >= E2*H) return;
    int e = tid >> 2, h = tid & 3;
    int dst = (e < N_EDGES) ? ei[N_EDGES+e] : e - N_EDGES;
    float v = expf(d_alpha[tid] - d_m[dst*H+h]);
    d_alpha[tid] = v;
    atomicAdd(&d_den[dst*H+h], v);
}

__global__ void k_agg(const int* __restrict__ ei) {
    int e = blockIdx.x, j = threadIdx.x;
    __shared__ float att[H];
    int src, dst;
    if (e < N_EDGES) { src = ei[e]; dst = ei[N_EDGES+e]; }
    else             { src = dst = e - N_EDGES; }
    if (j < H) att[j] = d_alpha[e*H+j] / d_den[dst*H+j];
    __syncthreads();
    float v = d_xp[(size_t)src*HC + j] * att[j >> 6];
    atomicAdd(&d_acc[(size_t)dst*HC + j], v);
}

__global__ void k_post(const float* __restrict__ convb) {
    int tid = blockIdx.x*blockDim.x + threadIdx.x;
    if (tid >= N_NODES*HD) return;
    int n = tid >> 6, c = tid & 63;
    const float* o = &d_acc[(size_t)n*HC];
    float s = o[c] + o[64+c] + o[128+c] + o[192+c];
    d_h[tid] = fmaxf(0.25f*s + convb[c], 0.f);
}

__global__ void k_pool(const int* __restrict__ batch) {
    int tid = blockIdx.x*blockDim.x + threadIdx.x;
    if (tid >= N_NODES*HD) return;
    int n = tid >> 6, c = tid & 63;
    int b = batch[n];
    atomicAdd(&d_pool[b*HD+c], d_h[tid]);
    if (c == 0) atomicAdd(&d_cnt[b], 1.f);
}

__global__ void k_head(const float* __restrict__ u,
                       const float* __restrict__ gW, const float* __restrict__ gb,
                       const float* __restrict__ f1W, const float* __restrict__ f1b,
                       const float* __restrict__ f2W, const float* __restrict__ f2b,
                       float* __restrict__ out) {
    int b = blockIdx.x, t = threadIdx.x;
    __shared__ float z[2*HD], z2[HD];
    float cn = fmaxf(d_cnt[b], 1.f);
    z[t] = d_pool[b*HD+t] / cn;
    float ug = gb[t];
    #pragma unroll
    for (int k = 0; k < 10; k++) ug += u[b*10+k]*gW[k*HD+t];
    z[HD+t] = fmaxf(ug, 0.f);
    __syncthreads();
    float v = f1b[t];
    #pragma unroll 8
    for (int k = 0; k < 2*HD; k++) v += z[k]*f1W[k*HD+t];
    z2[t] = fmaxf(v, 0.f);
    __syncthreads();
    if (t < 2) {
        float o = f2b[t];
        #pragma unroll 8
        for (int k = 0; k < HD; k++) o += z2[k]*f2W[k*2+t];
        out[b*2+t] = o;
    }
}

// ---------------- launch ----------------
extern "C" void kernel_launch(void* const* d_in, const int* in_sizes, int n_in,
                              void* d_out, int out_size) {
    const float* x      = (const float*)d_in[0];
    const int*   ei     = (const int*)  d_in[1];   // [2,E]
    const float* eattr  = (const float*)d_in[2];
    const float* u      = (const float*)d_in[3];
    const int*   batch  = (const int*)  d_in[4];
    const float* node_W = (const float*)d_in[5];
    const float* node_b = (const float*)d_in[6];
    const float* eemb_W = (const float*)d_in[7];
    const float* eemb_b = (const float*)d_in[8];
    const float* lin_W  = (const float*)d_in[9];
    const float* att_src= (const float*)d_in[10];
    const float* att_dst= (const float*)d_in[11];
    const float* lin_eW = (const float*)d_in[12];
    const float* att_e  = (const float*)d_in[13];
    const float* conv_b = (const float*)d_in[14];
    const float* gW     = (const float*)d_in[15];
    const float* gb     = (const float*)d_in[16];
    const float* f1W    = (const float*)d_in[17];
    const float* f1b    = (const float*)d_in[18];
    const float* f2W    = (const float*)d_in[19];
    const float* f2b    = (const float*)d_in[20];
    float* out = (float*)d_out;

    const int TB = 256;
    int gNH = (N_NODES*HD + TB-1)/TB;
    int gEH = (N_EDGES*HD + TB-1)/TB;
    int gE2H = (E2*H + TB-1)/TB;
    int gAED = (E2*L*H + TB-1)/TB;

    k_zero<<<gNH, TB>>>();
    k_node_embed<<<gNH, TB>>>(x, node_W, node_b);
    k_edge_embed<<<gEH, TB>>>(eattr, eemb_W, eemb_b);
    k_wevec<<<(L*H*HD + TB-1)/TB, TB>>>(lin_eW, att_e);
    k_degsum<<<gEH, TB>>>(ei);
    k_eaself<<<gNH, TB>>>();
    k_aed<<<gAED, TB>>>();

    for (int l = 0; l < L; l++) {
        k_xp<<<N_NODES, HC>>>(lin_W + (size_t)l*HD*HC,
                              att_src + l*HC, att_dst + l*HC);
        k_alpha<<<gE2H, TB>>>(ei, l);
        k_exp<<<gE2H, TB>>>(ei);
        k_agg<<<E2, HC>>>(ei);
        k_post<<<gNH, TB>>>(conv_b + l*C);
    }

    k_pool<<<gNH, TB>>>(batch);
    k_head<<<N_GRAPH, HD>>>(u, gW, gb, f1W, f1b, f2W, f2b, out);
}

// round 4
// speedup vs baseline: 2.1484x; 2.1484x over previous
#include <cuda_runtime.h>

#define N_NODES 20000
#define N_EDGES 320000
#define N_GRAPH 32
#define HD 64
#define H 4
#define C 64
#define L 3
#define HC (H*C)   // 256

// ---------------- scratch (static device globals; allocation-free) ----------------
static __device__ float d_h[N_NODES*HD];        // node features
static __device__ float d_xp[(size_t)N_NODES*HC];
static __device__ float d_ea[(size_t)N_EDGES*HD];
static __device__ float d_eaself[N_NODES*HD];
static __device__ float d_as[N_NODES*H];
static __device__ float d_ad[N_NODES*H];
static __device__ float d_pool[N_GRAPH*HD];
static __device__ float d_gcnt[N_GRAPH];
static __device__ float d_wevec[L*H*HD];        // We[:,hC:(h+1)C] @ a_e[h]

// CSR by destination
static __device__ int   d_ecnt[N_NODES];
static __device__ int   d_rstart[N_NODES];
static __device__ int   d_cursor[N_NODES];
static __device__ int   d_total;
static __device__ int   d_csrc[N_EDGES];        // src at csr position
static __device__ int   d_ceid[N_EDGES];        // original edge id at csr position
static __device__ float d_aedc[(size_t)L*N_EDGES*H]; // a_ed in csr order
static __device__ float d_aeds[L*N_NODES*H];         // a_ed for self loops

// ---------------- helpers ----------------
__device__ __forceinline__ void atomicMaxF_sh(float* addr, float val) {
    int old = __float_as_int(*addr);
    while (__int_as_float(old) < val) {
        int assumed = old;
        old = atomicCAS((int*)addr, assumed, __float_as_int(val));
        if (old == assumed) break;
    }
}
__device__ __forceinline__ float dot4(float4 a, float4 b) {
    return a.x*b.x + a.y*b.y + a.z*b.z + a.w*b.w;
}

// ---------------- kernels ----------------
__global__ void k_init() {
    int tid = blockIdx.x*blockDim.x + threadIdx.x;
    if (tid < N_NODES)    d_ecnt[tid] = 0;
    if (tid < N_GRAPH*HD) d_pool[tid] = 0.f;
    if (tid < N_GRAPH)    d_gcnt[tid] = 0.f;
    if (tid == 0)         d_total = 0;
}

__global__ void k_node_embed(const float* __restrict__ x,
                             const float* __restrict__ W,
                             const float* __restrict__ b) {
    int tid = blockIdx.x*blockDim.x + threadIdx.x;
    if (tid >= N_NODES*HD) return;
    int n = tid >> 6, j = tid & 63;
    float a = b[j];
    #pragma unroll
    for (int k = 0; k < 3; k++) a += x[n*3+k]*W[k*HD+j];
    d_h[tid] = fmaxf(a, 0.f);
}

__global__ void k_edge_embed(const float* __restrict__ eattr,
                             const float* __restrict__ W,
                             const float* __restrict__ b) {
    int tid = blockIdx.x*blockDim.x + threadIdx.x;
    if (tid >= N_EDGES*HD) return;
    int e = tid >> 6, j = tid & 63;
    float a = b[j];
    #pragma unroll
    for (int k = 0; k < 4; k++) a += eattr[e*4+k]*W[k*HD+j];
    d_ea[tid] = fmaxf(a, 0.f);
}

// wevec[l,h,k] = sum_c lin_eW[l][k, h*C+c] * att_e[l][h,c]
__global__ void k_wevec(const float* __restrict__ lin_eW,
                        const float* __restrict__ att_e) {
    int tid = blockIdx.x*blockDim.x + threadIdx.x;
    if (tid >= L*H*HD) return;
    int l = tid / (H*HD), r = tid % (H*HD), h = r / HD, k = r % HD;
    const float* We = lin_eW + (size_t)l*HD*HC;
    const float* ae = att_e + l*HC;
    float a = 0.f;
    #pragma unroll 8
    for (int c = 0; c < C; c++) a += We[k*HC + h*C + c]*ae[h*C + c];
    d_wevec[tid] = a;
}

// ---- CSR build ----
__global__ void k_count(const int* __restrict__ ei) {
    int tid = blockIdx.x*blockDim.x + threadIdx.x;
    if (tid >= N_EDGES) return;
    atomicAdd(&d_ecnt[ei[N_EDGES + tid]], 1);
}
__global__ void k_ranges() {
    int tid = blockIdx.x*blockDim.x + threadIdx.x;
    if (tid >= N_NODES) return;
    int c = d_ecnt[tid];
    int s = atomicAdd(&d_total, c);
    d_rstart[tid] = s;
    d_cursor[tid] = s;
}
__global__ void k_scatter(const int* __restrict__ ei) {
    int tid = blockIdx.x*blockDim.x + threadIdx.x;
    if (tid >= N_EDGES) return;
    int dst = ei[N_EDGES + tid];
    int pos = atomicAdd(&d_cursor[dst], 1);
    d_csrc[pos] = ei[tid];
    d_ceid[pos] = tid;
}

// ea_self via gather: 4 nodes per block, 64 threads (channels) per node
__global__ void k_eaself_g() {
    int n = blockIdx.x*4 + (threadIdx.x >> 6);
    int j = threadIdx.x & 63;
    if (n >= N_NODES) return;
    int start = d_rstart[n], cnt = d_ecnt[n];
    float a = 0.f;
    for (int i = 0; i < cnt; i++) {
        int e = d_ceid[start + i];
        a += d_ea[(size_t)e*HD + j];
    }
    d_eaself[n*HD + j] = a / fmaxf((float)cnt, 1.f);
}

// a_ed for real edges, written in CSR order. 4 lanes cooperate per edge.
__global__ void k_aed2() {
    __shared__ float wv[L*H*HD];   // 768 floats
    for (int i = threadIdx.x; i < L*H*HD; i += 256) wv[i] = d_wevec[i];
    __syncthreads();
    int g = blockIdx.x*64 + (threadIdx.x >> 2);
    int lane = threadIdx.x & 3;
    if (g >= N_EDGES) return;
    int e = d_ceid[g];
    const float4* row = (const float4*)&d_ea[(size_t)e*HD];
    float4 r0 = row[lane*4+0], r1 = row[lane*4+1], r2 = row[lane*4+2], r3 = row[lane*4+3];
    float v[L*H];
    #pragma unroll
    for (int lh = 0; lh < L*H; lh++) {
        const float4* w = (const float4*)&wv[lh*HD + lane*16];
        v[lh] = dot4(r0, w[0]) + dot4(r1, w[1]) + dot4(r2, w[2]) + dot4(r3, w[3]);
    }
    #pragma unroll
    for (int lh = 0; lh < L*H; lh++) {
        v[lh] += __shfl_xor_sync(0xffffffffu, v[lh], 1);
        v[lh] += __shfl_xor_sync(0xffffffffu, v[lh], 2);
    }
    #pragma unroll
    for (int l = 0; l < L; l++)
        d_aedc[((size_t)l*N_EDGES + g)*H + lane] = v[l*H + lane];
}

// a_ed for self loops
__global__ void k_aeds() {
    int tid = blockIdx.x*blockDim.x + threadIdx.x;
    if (tid >= N_NODES*L*H) return;
    int n = tid / (L*H), r = tid % (L*H);
    const float* row = &d_eaself[n*HD];
    const float* w = &d_wevec[r*HD];
    float a = 0.f;
    #pragma unroll 8
    for (int k = 0; k < HD; k++) a += row[k]*w[k];
    d_aeds[((r >> 2)*N_NODES + n)*H + (r & 3)] = a;
}

// per-layer: xp = h @ W, a_src/a_dst reductions
__global__ void k_xp(const float* __restrict__ linW,
                     const float* __restrict__ asrc,
                     const float* __restrict__ adst) {
    int n = blockIdx.x, j = threadIdx.x;
    __shared__ float hrow[HD];
    __shared__ float wss[8], wsd[8];
    if (j < HD) hrow[j] = d_h[n*HD+j];
    __syncthreads();
    float a = 0.f;
    #pragma unroll 16
    for (int k = 0; k < HD; k++) a += hrow[k]*linW[k*HC+j];
    d_xp[(size_t)n*HC+j] = a;
    float ps = a * asrc[j];
    float pd = a * adst[j];
    #pragma unroll
    for (int o = 16; o > 0; o >>= 1) {
        ps += __shfl_down_sync(0xffffffffu, ps, o);
        pd += __shfl_down_sync(0xffffffffu, pd, o);
    }
    int w = j >> 5;
    if ((j & 31) == 0) { wss[w] = ps; wsd[w] = pd; }
    __syncthreads();
    if (j < H) {
        d_as[n*H+j] = wss[2*j] + wss[2*j+1];
        d_ad[n*H+j] = wsd[2*j] + wsd[2*j+1];
    }
}

// Fused layer: alpha + segment softmax + aggregation + head-mean + bias + relu.
// One block per destination node; thread j owns output channel j (head = j>>6).
__global__ void k_layer(int l, const float* __restrict__ convb) {
    int n = blockIdx.x, j = threadIdx.x;
    int h = j >> 6;
    __shared__ float sm_m[H], sm_den[H], sm_aself[H];
    __shared__ float sm_acc[HC];
    int start = d_rstart[n];
    int cnt = d_ecnt[n];
    const float* aedl = d_aedc + (size_t)l*N_EDGES*H;

    if (j < H) {
        float a = d_as[n*H+j] + d_ad[n*H+j] + d_aeds[(l*N_NODES + n)*H + j];
        a = (a > 0.f) ? a : 0.2f*a;
        sm_aself[j] = a;
        sm_m[j] = a;
    }
    __syncthreads();

    // Pass A: per-head max over incoming edges
    for (int i = j; i < cnt*H; i += HC) {
        int pos = start + (i >> 2); int hh = i & 3;
        int src = d_csrc[pos];
        float a = d_as[src*H+hh] + d_ad[n*H+hh] + aedl[(size_t)pos*H + hh];
        a = (a > 0.f) ? a : 0.2f*a;
        atomicMaxF_sh(&sm_m[hh], a);
    }
    __syncthreads();

    // Pass B: weighted gather with unnormalized weights
    float mh  = sm_m[h];
    float adn = d_ad[n*H+h];
    float wself = __expf(sm_aself[h] - mh);
    float acc = wself * d_xp[(size_t)n*HC + j];
    float den = wself;
    for (int i = 0; i < cnt; i++) {
        int pos = start + i;
        int src = d_csrc[pos];                        // uniform per warp
        float a = d_as[src*H+h] + adn + aedl[(size_t)pos*H + h];
        a = (a > 0.f) ? a : 0.2f*a;
        float w = __expf(a - mh);
        acc += w * d_xp[(size_t)src*HC + j];
        den += w;
    }
    if ((j & 63) == 0) sm_den[h] = den;
    __syncthreads();
    sm_acc[j] = acc / sm_den[h];
    __syncthreads();
    if (j < HD) {
        float s = sm_acc[j] + sm_acc[j+64] + sm_acc[j+128] + sm_acc[j+192];
        d_h[n*HD + j] = fmaxf(0.25f*s + convb[j], 0.f);
    }
}

__global__ void k_pool(const int* __restrict__ batch) {
    int tid = blockIdx.x*blockDim.x + threadIdx.x;
    if (tid >= N_NODES*HD) return;
    int n = tid >> 6, c = tid & 63;
    int b = batch[n];
    atomicAdd(&d_pool[b*HD+c], d_h[tid]);
    if (c == 0) atomicAdd(&d_gcnt[b], 1.f);
}

__global__ void k_head(const float* __restrict__ u,
                       const float* __restrict__ gW, const float* __restrict__ gb,
                       const float* __restrict__ f1W, const float* __restrict__ f1b,
                       const float* __restrict__ f2W, const float* __restrict__ f2b,
                       float* __restrict__ out) {
    int b = blockIdx.x, t = threadIdx.x;
    __shared__ float z[2*HD], z2[HD];
    float cn = fmaxf(d_gcnt[b], 1.f);
    z[t] = d_pool[b*HD+t] / cn;
    float ug = gb[t];
    #pragma unroll
    for (int k = 0; k < 10; k++) ug += u[b*10+k]*gW[k*HD+t];
    z[HD+t] = fmaxf(ug, 0.f);
    __syncthreads();
    float v = f1b[t];
    #pragma unroll 8
    for (int k = 0; k < 2*HD; k++) v += z[k]*f1W[k*HD+t];
    z2[t] = fmaxf(v, 0.f);
    __syncthreads();
    if (t < 2) {
        float o = f2b[t];
        #pragma unroll 8
        for (int k = 0; k < HD; k++) o += z2[k]*f2W[k*2+t];
        out[b*2+t] = o;
    }
}

// ---------------- launch ----------------
extern "C" void kernel_launch(void* const* d_in, const int* in_sizes, int n_in,
                              void* d_out, int out_size) {
    const float* x      = (const float*)d_in[0];
    const int*   ei     = (const int*)  d_in[1];   // [2,E]
    const float* eattr  = (const float*)d_in[2];
    const float* u      = (const float*)d_in[3];
    const int*   batch  = (const int*)  d_in[4];
    const float* node_W = (const float*)d_in[5];
    const float* node_b = (const float*)d_in[6];
    const float* eemb_W = (const float*)d_in[7];
    const float* eemb_b = (const float*)d_in[8];
    const float* lin_W  = (const float*)d_in[9];
    const float* att_src= (const float*)d_in[10];
    const float* att_dst= (const float*)d_in[11];
    const float* lin_eW = (const float*)d_in[12];
    const float* att_e  = (const float*)d_in[13];
    const float* conv_b = (const float*)d_in[14];
    const float* gW     = (const float*)d_in[15];
    const float* gb     = (const float*)d_in[16];
    const float* f1W    = (const float*)d_in[17];
    const float* f1b    = (const float*)d_in[18];
    const float* f2W    = (const float*)d_in[19];
    const float* f2b    = (const float*)d_in[20];
    float* out = (float*)d_out;

    const int TB = 256;
    int gNH = (N_NODES*HD + TB-1)/TB;
    int gEH = (N_EDGES*HD + TB-1)/TB;
    int gE  = (N_EDGES + TB-1)/TB;
    int gN  = (N_NODES + TB-1)/TB;

    k_init<<<gN, TB>>>();
    k_node_embed<<<gNH, TB>>>(x, node_W, node_b);
    k_edge_embed<<<gEH, TB>>>(eattr, eemb_W, eemb_b);
    k_wevec<<<(L*H*HD + TB-1)/TB, TB>>>(lin_eW, att_e);

    // CSR build
    k_count<<<gE, TB>>>(ei);
    k_ranges<<<gN, TB>>>();
    k_scatter<<<gE, TB>>>(ei);

    // edge attention terms (all layers)
    k_eaself_g<<<(N_NODES + 3)/4, TB>>>();
    k_aed2<<<(N_EDGES + 63)/64, TB>>>();
    k_aeds<<<(N_NODES*L*H + TB-1)/TB, TB>>>();

    for (int l = 0; l < L; l++) {
        k_xp<<<N_NODES, HC>>>(lin_W + (size_t)l*HD*HC,
                              att_src + l*HC, att_dst + l*HC);
        k_layer<<<N_NODES, HC>>>(l, conv_b + l*C);
    }

    k_pool<<<gNH, TB>>>(batch);
    k_head<<<N_GRAPH, HD>>>(u, gW, gb, f1W, f1b, f2W, f2b, out);
}

// round 5
// speedup vs baseline: 4.0339x; 1.8776x over previous
#include <cuda_runtime.h>

#define N_NODES 20000
#define N_EDGES 320000
#define N_GRAPH 32
#define HD 64
#define H 4
#define C 64
#define L 3
#define HC (H*C)   // 256
#define LH (L*H)   // 12
#define MAXD 256   // smem-cached max in-degree in k_layer (fallback path beyond)

// ---------------- scratch (static device globals; allocation-free) ----------------
static __device__ float d_h[N_NODES*HD];
static __device__ float d_xp[(size_t)N_NODES*HC];
static __device__ float d_as[N_NODES*H];
static __device__ float d_ad[N_NODES*H];
static __device__ float d_pool[N_GRAPH*HD];
static __device__ float d_gcnt[N_GRAPH];
static __device__ float d_wevec[L*H*HD];             // We[:,hC:(h+1)C] @ a_e[h]

// CSR by destination
static __device__ int   d_ecnt[N_NODES];
static __device__ int   d_rstart[N_NODES];
static __device__ int   d_cursor[N_NODES];
static __device__ int   d_total;
static __device__ int   d_csrc[N_EDGES];             // src at csr position
static __device__ int   d_ceid[N_EDGES];             // original edge id at csr position
static __device__ float d_aedc[(size_t)L*N_EDGES*H]; // a_ed in csr order [(l*E+pos)*4+h]
static __device__ float d_aeds[L*N_NODES*H];         // self-loop a_ed [(l*N+n)*4+h]

// ---------------- kernels ----------------
__global__ void k_init() {
    int tid = blockIdx.x*blockDim.x + threadIdx.x;
    if (tid < N_NODES)    d_ecnt[tid] = 0;
    if (tid < N_GRAPH*HD) d_pool[tid] = 0.f;
    if (tid < N_GRAPH)    d_gcnt[tid] = 0.f;
    if (tid == 0)         d_total = 0;
}

__global__ void k_node_embed(const float* __restrict__ x,
                             const float* __restrict__ W,
                             const float* __restrict__ b) {
    int tid = blockIdx.x*blockDim.x + threadIdx.x;
    if (tid >= N_NODES*HD) return;
    int n = tid >> 6, j = tid & 63;
    float a = b[j];
    #pragma unroll
    for (int k = 0; k < 3; k++) a += x[n*3+k]*W[k*HD+j];
    d_h[tid] = fmaxf(a, 0.f);
}

// wevec[l,h,k] = sum_c lin_eW[l][k, h*C+c] * att_e[l][h,c]
// one block per layer; stage We (64KB) in smem with pad to avoid bank conflicts
__global__ void k_wevec(const float* __restrict__ lin_eW,
                        const float* __restrict__ att_e) {
    __shared__ float swe[HD*(HC+1)];   // [k][256+pad]
    __shared__ float sae[HC];
    int l = blockIdx.x, t = threadIdx.x;
    const float* We = lin_eW + (size_t)l*HD*HC;
    for (int i = t; i < HD*HC; i += 256) {
        int k = i >> 8, r = i & 255;
        swe[k*(HC+1) + r] = We[i];
    }
    if (t < HC) sae[t] = att_e[l*HC + t];
    __syncthreads();
    int h = t >> 6, k = t & 63;
    float a = 0.f;
    #pragma unroll 8
    for (int c = 0; c < C; c++) a += swe[k*(HC+1) + h*C + c]*sae[h*C + c];
    d_wevec[l*H*HD + h*HD + k] = a;
}

// ---- CSR build ----
__global__ void k_count(const int* __restrict__ ei) {
    int tid = blockIdx.x*blockDim.x + threadIdx.x;
    if (tid >= N_EDGES) return;
    atomicAdd(&d_ecnt[ei[N_EDGES + tid]], 1);
}
__global__ void k_ranges() {
    int tid = blockIdx.x*blockDim.x + threadIdx.x;
    if (tid >= N_NODES) return;
    int c = d_ecnt[tid];
    int s = atomicAdd(&d_total, c);
    d_rstart[tid] = s;
    d_cursor[tid] = s;
}
__global__ void k_scatter(const int* __restrict__ ei) {
    int tid = blockIdx.x*blockDim.x + threadIdx.x;
    if (tid >= N_EDGES) return;
    int dst = ei[N_EDGES + tid];
    int pos = atomicAdd(&d_cursor[dst], 1);
    d_csrc[pos] = ei[tid];
    d_ceid[pos] = tid;
}

// Fused: edge embedding (registers only) -> a_ed for all L layers, in CSR order.
// d_ea never materialized.
__global__ void __launch_bounds__(256) k_aed(const float* __restrict__ eattr,
                                             const float* __restrict__ W,
                                             const float* __restrict__ b) {
    __shared__ float sW[4*HD];      // [k][c]
    __shared__ float sb[HD];
    __shared__ float swv[LH*HD];    // 768
    int t = threadIdx.x;
    if (t < 4*HD) sW[t] = W[t];
    if (t < HD)   sb[t] = b[t];
    for (int i = t; i < LH*HD; i += 256) swv[i] = d_wevec[i];
    __syncthreads();

    int g = blockIdx.x*blockDim.x + t;
    if (g >= N_EDGES) return;
    int e = d_ceid[g];
    float4 ua = ((const float4*)eattr)[e];

    float ea[HD];
    #pragma unroll
    for (int c = 0; c < HD; c++) {
        float v = sb[c];
        v = fmaf(ua.x, sW[0*HD+c], v);
        v = fmaf(ua.y, sW[1*HD+c], v);
        v = fmaf(ua.z, sW[2*HD+c], v);
        v = fmaf(ua.w, sW[3*HD+c], v);
        ea[c] = fmaxf(v, 0.f);
    }
    float acc[LH];
    #pragma unroll
    for (int lh = 0; lh < LH; lh++) {
        const float4* wv4 = (const float4*)&swv[lh*HD];
        float s = 0.f;
        #pragma unroll
        for (int c4 = 0; c4 < 16; c4++) {
            float4 w = wv4[c4];
            s = fmaf(ea[c4*4+0], w.x, s);
            s = fmaf(ea[c4*4+1], w.y, s);
            s = fmaf(ea[c4*4+2], w.z, s);
            s = fmaf(ea[c4*4+3], w.w, s);
        }
        acc[lh] = s;
    }
    #pragma unroll
    for (int l = 0; l < L; l++) {
        float4 o = make_float4(acc[l*4+0], acc[l*4+1], acc[l*4+2], acc[l*4+3]);
        ((float4*)d_aedc)[(size_t)l*N_EDGES + g] = o;
    }
}

// Self-loop a_ed = mean of incoming a_ed (linearity of wevec dot).
// thread = (l, n), streams float4 over the node's CSR range.
__global__ void k_aeds() {
    int tid = blockIdx.x*blockDim.x + threadIdx.x;
    if (tid >= L*N_NODES) return;
    int l = tid / N_NODES, n = tid % N_NODES;
    int start = d_rstart[n], cnt = d_ecnt[n];
    const float4* a4 = (const float4*)d_aedc + (size_t)l*N_EDGES;
    float4 s = make_float4(0.f, 0.f, 0.f, 0.f);
    for (int i = 0; i < cnt; i++) {
        float4 v = a4[start + i];
        s.x += v.x; s.y += v.y; s.z += v.z; s.w += v.w;
    }
    float inv = 1.f / fmaxf((float)cnt, 1.f);
    s.x *= inv; s.y *= inv; s.z *= inv; s.w *= inv;
    ((float4*)d_aeds)[l*N_NODES + n] = s;
}

// per-layer: xp = h @ W + a_src/a_dst reductions. 4 nodes per block to amortize lin_W.
__global__ void k_xp(const float* __restrict__ linW,
                     const float* __restrict__ asrc,
                     const float* __restrict__ adst) {
    int n0 = blockIdx.x*4, j = threadIdx.x;
    __shared__ float hrow[4][HD];
    __shared__ float sms[8][4], smd[8][4];
    hrow[j >> 6][j & 63] = d_h[n0*HD + j];
    __syncthreads();
    float a0 = 0.f, a1 = 0.f, a2 = 0.f, a3 = 0.f;
    #pragma unroll 16
    for (int k = 0; k < HD; k++) {
        float w = linW[k*HC + j];
        a0 = fmaf(hrow[0][k], w, a0);
        a1 = fmaf(hrow[1][k], w, a1);
        a2 = fmaf(hrow[2][k], w, a2);
        a3 = fmaf(hrow[3][k], w, a3);
    }
    d_xp[(size_t)(n0+0)*HC + j] = a0;
    d_xp[(size_t)(n0+1)*HC + j] = a1;
    d_xp[(size_t)(n0+2)*HC + j] = a2;
    d_xp[(size_t)(n0+3)*HC + j] = a3;
    float as_ = asrc[j], ad_ = adst[j];
    float ps[4] = {a0*as_, a1*as_, a2*as_, a3*as_};
    float pd[4] = {a0*ad_, a1*ad_, a2*ad_, a3*ad_};
    #pragma unroll
    for (int o = 16; o > 0; o >>= 1) {
        #pragma unroll
        for (int m = 0; m < 4; m++) {
            ps[m] += __shfl_down_sync(0xffffffffu, ps[m], o);
            pd[m] += __shfl_down_sync(0xffffffffu, pd[m], o);
        }
    }
    int w = j >> 5;
    if ((j & 31) == 0) {
        #pragma unroll
        for (int m = 0; m < 4; m++) { sms[w][m] = ps[m]; smd[w][m] = pd[m]; }
    }
    __syncthreads();
    if (j < 16) {
        int m = j >> 2, hh = j & 3;
        d_as[(n0+m)*H + hh] = sms[2*hh][m] + sms[2*hh+1][m];
    } else if (j < 32) {
        int tt = j - 16, m = tt >> 2, hh = tt & 3;
        d_ad[(n0+m)*H + hh] = smd[2*hh][m] + smd[2*hh+1][m];
    }
}

// Fused layer: alpha + segment softmax + aggregation + head-mean + bias + relu.
// Block per dst node; thread j owns channel j (head = j>>6).
__global__ void __launch_bounds__(256) k_layer(int l, const float* __restrict__ convb) {
    int n = blockIdx.x, j = threadIdx.x;
    int h = j >> 6, i0 = j & 63;
    __shared__ float sm_alpha[H*MAXD];
    __shared__ int   sm_src[MAXD];
    __shared__ float sm_wmax[8];
    __shared__ float sm_m[H], sm_aself[H];
    __shared__ float sm_acc[HC];

    int start = d_rstart[n], cnt = d_ecnt[n];
    bool fits = (cnt <= MAXD);
    float adn = d_ad[n*H + h];
    const float* aedl = d_aedc + (size_t)l*N_EDGES*H;

    if (j < H) {
        float a = d_as[n*H+j] + d_ad[n*H+j] + d_aeds[(l*N_NODES + n)*H + j];
        sm_aself[j] = (a > 0.f) ? a : 0.2f*a;
    }

    // Pass A: compute alphas (cache in smem), per-thread max
    float lmax = -1e30f;
    for (int i = i0; i < cnt; i += 64) {
        int src = d_csrc[start + i];
        float a = d_as[src*H + h] + adn + aedl[(size_t)(start+i)*H + h];
        a = (a > 0.f) ? a : 0.2f*a;
        if (fits) {
            sm_alpha[h*MAXD + i] = a;
            if (h == 0) sm_src[i] = src;
        }
        lmax = fmaxf(lmax, a);
    }
    #pragma unroll
    for (int o = 16; o > 0; o >>= 1)
        lmax = fmaxf(lmax, __shfl_xor_sync(0xffffffffu, lmax, o));
    if ((j & 31) == 0) sm_wmax[j >> 5] = lmax;
    __syncthreads();
    if (j < H) sm_m[j] = fmaxf(sm_aself[j], fmaxf(sm_wmax[2*j], sm_wmax[2*j+1]));
    __syncthreads();

    // Pass B: weighted gather
    float mh = sm_m[h];
    float wself = __expf(sm_aself[h] - mh);
    float den = wself;
    float acc = wself * d_xp[(size_t)n*HC + j];
    if (fits) {
        for (int i = 0; i < cnt; i++) {
            float w = __expf(sm_alpha[h*MAXD + i] - mh);
            int src = sm_src[i];
            acc = fmaf(w, d_xp[(size_t)src*HC + j], acc);
            den += w;
        }
    } else {
        for (int i = 0; i < cnt; i++) {
            int src = d_csrc[start + i];
            float a = d_as[src*H + h] + adn + aedl[(size_t)(start+i)*H + h];
            a = (a > 0.f) ? a : 0.2f*a;
            float w = __expf(a - mh);
            acc = fmaf(w, d_xp[(size_t)src*HC + j], acc);
            den += w;
        }
    }
    sm_acc[j] = acc / den;
    __syncthreads();
    if (j < HD) {
        float s = sm_acc[j] + sm_acc[j+64] + sm_acc[j+128] + sm_acc[j+192];
        d_h[n*HD + j] = fmaxf(0.25f*s + convb[j], 0.f);
    }
}

__global__ void k_pool(const int* __restrict__ batch) {
    int tid = blockIdx.x*blockDim.x + threadIdx.x;
    if (tid >= N_NODES*HD) return;
    int n = tid >> 6, c = tid & 63;
    int b = batch[n];
    atomicAdd(&d_pool[b*HD+c], d_h[tid]);
    if (c == 0) atomicAdd(&d_gcnt[b], 1.f);
}

__global__ void k_head(const float* __restrict__ u,
                       const float* __restrict__ gW, const float* __restrict__ gb,
                       const float* __restrict__ f1W, const float* __restrict__ f1b,
                       const float* __restrict__ f2W, const float* __restrict__ f2b,
                       float* __restrict__ out) {
    int b = blockIdx.x, t = threadIdx.x;
    __shared__ float z[2*HD], z2[HD];
    float cn = fmaxf(d_gcnt[b], 1.f);
    z[t] = d_pool[b*HD+t] / cn;
    float ug = gb[t];
    #pragma unroll
    for (int k = 0; k < 10; k++) ug += u[b*10+k]*gW[k*HD+t];
    z[HD+t] = fmaxf(ug, 0.f);
    __syncthreads();
    float v = f1b[t];
    #pragma unroll 8
    for (int k = 0; k < 2*HD; k++) v += z[k]*f1W[k*HD+t];
    z2[t] = fmaxf(v, 0.f);
    __syncthreads();
    if (t < 2) {
        float o = f2b[t];
        #pragma unroll 8
        for (int k = 0; k < HD; k++) o += z2[k]*f2W[k*2+t];
        out[b*2+t] = o;
    }
}

// ---------------- launch ----------------
extern "C" void kernel_launch(void* const* d_in, const int* in_sizes, int n_in,
                              void* d_out, int out_size) {
    const float* x      = (const float*)d_in[0];
    const int*   ei     = (const int*)  d_in[1];   // [2,E]
    const float* eattr  = (const float*)d_in[2];
    const float* u      = (const float*)d_in[3];
    const int*   batch  = (const int*)  d_in[4];
    const float* node_W = (const float*)d_in[5];
    const float* node_b = (const float*)d_in[6];
    const float* eemb_W = (const float*)d_in[7];
    const float* eemb_b = (const float*)d_in[8];
    const float* lin_W  = (const float*)d_in[9];
    const float* att_src= (const float*)d_in[10];
    const float* att_dst= (const float*)d_in[11];
    const float* lin_eW = (const float*)d_in[12];
    const float* att_e  = (const float*)d_in[13];
    const float* conv_b = (const float*)d_in[14];
    const float* gW     = (const float*)d_in[15];
    const float* gb     = (const float*)d_in[16];
    const float* f1W    = (const float*)d_in[17];
    const float* f1b    = (const float*)d_in[18];
    const float* f2W    = (const float*)d_in[19];
    const float* f2b    = (const float*)d_in[20];
    float* out = (float*)d_out;

    const int TB = 256;
    int gNH = (N_NODES*HD + TB-1)/TB;
    int gE  = (N_EDGES + TB-1)/TB;
    int gN  = (N_NODES + TB-1)/TB;

    k_init<<<gN, TB>>>();
    k_node_embed<<<gNH, TB>>>(x, node_W, node_b);
    k_wevec<<<L, TB>>>(lin_eW, att_e);

    // CSR build
    k_count<<<gE, TB>>>(ei);
    k_ranges<<<gN, TB>>>();
    k_scatter<<<gE, TB>>>(ei);

    // edge attention terms for all layers (edge embedding fused, never stored)
    k_aed<<<gE, TB>>>(eattr, eemb_W, eemb_b);
    k_aeds<<<(L*N_NODES + TB-1)/TB, TB>>>();

    for (int l = 0; l < L; l++) {
        k_xp<<<N_NODES/4, HC>>>(lin_W + (size_t)l*HD*HC,
                                att_src + l*HC, att_dst + l*HC);
        k_layer<<<N_NODES, HC>>>(l, conv_b + l*C);
    }

    k_pool<<<gNH, TB>>>(batch);
    k_head<<<N_GRAPH, HD>>>(u, gW, gb, f1W, f1b, f2W, f2b, out);
}